// round 7
// baseline (speedup 1.0000x reference)
#include <cuda_runtime.h>
#include <cuda_bf16.h>
#include <math.h>
#include <cstdint>

#define NGENE 50000
#define NDIS  25000
#define FGENE 512
#define FDIS  256
#define CH    128
#define NE    150000

// ---------------- scratch (static device globals; no allocation) ----------------
__device__ float  g_xs[(size_t)NGENE * 512];
__device__ float  g_agg[(size_t)NGENE * CH];
__device__ float  g_ls[NGENE * 4];
__device__ float  g_ld[NGENE * 4];
__device__ float  g_logits[(NE + NGENE) * 4];
__device__ float  g_denom[NGENE * 4];
__device__ float  g_wld[512];
__device__ double g_sum[CH];
__device__ double g_sumsq[CH];
__device__ float  g_scale[CH];
__device__ float  g_shift[CH];
__device__ __align__(256) __nv_bfloat16 g_ahi[(size_t)NGENE * CH];
__device__ __align__(256) __nv_bfloat16 g_alo[(size_t)NGENE * CH];
__device__ __align__(256) __nv_bfloat16 g_bthi[512 * 128];
__device__ __align__(256) __nv_bfloat16 g_btlo[512 * 128];

// ---------------- small helpers ----------------
__device__ __forceinline__ float leaky(float x) { return x > 0.f ? x : 0.2f * x; }
__device__ __forceinline__ uint32_t smem_u32(const void* p) {
    uint32_t a;
    asm("{ .reg .u64 t; cvta.to.shared.u64 t, %1; cvt.u32.u64 %0, t; }" : "=r"(a) : "l"(p));
    return a;
}
__device__ __forceinline__ void mma16816(float* c, const uint32_t* a,
                                         uint32_t b0, uint32_t b1) {
    asm volatile("mma.sync.aligned.m16n8k16.row.col.f32.bf16.bf16.f32 "
                 "{%0,%1,%2,%3}, {%4,%5,%6,%7}, {%8,%9}, {%0,%1,%2,%3};"
                 : "+f"(c[0]), "+f"(c[1]), "+f"(c[2]), "+f"(c[3])
                 : "r"(a[0]), "r"(a[1]), "r"(a[2]), "r"(a[3]), "r"(b0), "r"(b1));
}
__device__ __forceinline__ void ldmx4(uint32_t* r, uint32_t addr) {
    asm volatile("ldmatrix.sync.aligned.m8n8.x4.shared.b16 {%0,%1,%2,%3}, [%4];"
                 : "=r"(r[0]), "=r"(r[1]), "=r"(r[2]), "=r"(r[3]) : "r"(addr));
}
__device__ __forceinline__ void cp16(uint32_t saddr, const void* g) {
    asm volatile("cp.async.cg.shared.global [%0], [%1], 16;" :: "r"(saddr), "l"(g));
}
__device__ __forceinline__ void cp_commit() {
    asm volatile("cp.async.commit_group;" ::: "memory");
}
template <int N_>
__device__ __forceinline__ void cp_wait() {
    asm volatile("cp.async.wait_group %0;" :: "n"(N_) : "memory");
}
__device__ __forceinline__ uint32_t pack_bf2(float x, float y) {
    __nv_bfloat162 t(__float2bfloat16(x), __float2bfloat16(y));
    return *(uint32_t*)&t;
}

// B [K,N] fp32 -> Bt hi/lo [N,K] bf16 (transpose; tiny)
__global__ void split_bt_kernel(const float* __restrict__ B,
                                __nv_bfloat16* __restrict__ thi,
                                __nv_bfloat16* __restrict__ tlo, int K, int N) {
    int idx = blockIdx.x * blockDim.x + threadIdx.x;
    if (idx >= K * N) return;
    int k = idx / N, n = idx % N;
    float v = B[idx];
    __nv_bfloat16 h = __float2bfloat16(v);
    thi[(size_t)n * K + k] = h;
    tlo[(size_t)n * K + k] = __float2bfloat16(v - __bfloat162float(h));
}

// ---------------- split-bf16 GEMM ----------------
// A path A (fp32, in-register split) XOR path Ahi/Alo (pre-split, cp.async).
// flags: 1=bias, 2=relu, 4=fused ls, 8=fused colsum
#define SST 40

__global__ __launch_bounds__(256, 2)
void gemm_mma_kernel(const float* __restrict__ A,
                     const __nv_bfloat16* __restrict__ Ahi,
                     const __nv_bfloat16* __restrict__ Alo,
                     const __nv_bfloat16* __restrict__ Bthi,
                     const __nv_bfloat16* __restrict__ Btlo,
                     const float* __restrict__ bias, const float* __restrict__ a_s,
                     float* __restrict__ C, int M, int N, int K, int flags)
{
    __shared__ __align__(16) __nv_bfloat16 smem[2][4][128 * SST];  // Ah, Al, Bh, Bl
    __shared__ float cs[128], cq[128];

    const int tid = threadIdx.x, wid = tid >> 5, lane = tid & 31;
    const int bm = blockIdx.y * 128, bn = blockIdx.x * 128;
    const int wm = (wid & 3) * 32, wn = (wid >> 2) * 64;
    const int lr = lane >> 2, lc = (lane & 3) * 2;
    const uint32_t sbase = smem_u32(&smem[0][0][0]);
    const uint32_t tilebytes = 128 * SST * 2;
    const bool presplit = (Ahi != nullptr);

    if ((flags & 8) && tid < 128) { cs[tid] = 0.f; cq[tid] = 0.f; }

    float acc[2][8][4];
#pragma unroll
    for (int mt = 0; mt < 2; mt++)
#pragma unroll
        for (int nt = 0; nt < 8; nt++)
#pragma unroll
            for (int j = 0; j < 4; j++) acc[mt][nt][j] = 0.f;

    // cp.async coords (A presplit and B): 128 rows x 32 cols bf16, 2 halves
    const int br_ = tid >> 2, bc8_ = (tid & 3) * 8;
    // fp32-A LDG coords
    const int ar = tid >> 1, ac = (tid & 1) * 16;
    const int agr = (bm + ar < M) ? (bm + ar) : (M - 1);
    // presplit-A clamped row
    const int apr = (bm + br_ < M) ? (bm + br_) : (M - 1);
    const int apr2 = (bm + br_ + 64 < M) ? (bm + br_ + 64) : (M - 1);

    float av[16];

    auto ldgA = [&](int k0) {
        const float4* p = (const float4*)(A + (size_t)agr * K + k0 + ac);
        float4 v0 = p[0], v1 = p[1], v2 = p[2], v3 = p[3];
        av[0] = v0.x; av[1] = v0.y; av[2] = v0.z; av[3] = v0.w;
        av[4] = v1.x; av[5] = v1.y; av[6] = v1.z; av[7] = v1.w;
        av[8] = v2.x; av[9] = v2.y; av[10] = v2.z; av[11] = v2.w;
        av[12] = v3.x; av[13] = v3.y; av[14] = v3.z; av[15] = v3.w;
    };
    auto stsA = [&](int buf) {
        uint32_t hi[8], lo[8];
#pragma unroll
        for (int j = 0; j < 8; j++) {
            float x0 = av[2 * j], x1 = av[2 * j + 1];
            __nv_bfloat16 h0 = __float2bfloat16(x0), h1 = __float2bfloat16(x1);
            hi[j] = pack_bf2(x0, x1);
            lo[j] = pack_bf2(x0 - __bfloat162float(h0), x1 - __bfloat162float(h1));
        }
        char* base = (char*)&smem[buf][0][0];
        const uint32_t off = (uint32_t)(ar * SST + ac) * 2;
        *(uint4*)(base + off)      = make_uint4(hi[0], hi[1], hi[2], hi[3]);
        *(uint4*)(base + off + 16) = make_uint4(hi[4], hi[5], hi[6], hi[7]);
        char* basel = (char*)&smem[buf][1][0];
        *(uint4*)(basel + off)      = make_uint4(lo[0], lo[1], lo[2], lo[3]);
        *(uint4*)(basel + off + 16) = make_uint4(lo[4], lo[5], lo[6], lo[7]);
    };
    auto issueA = [&](int buf, int k0) {   // presplit path
#pragma unroll
        for (int h = 0; h < 2; h++) {
            const int r = br_ + h * 64;
            const int gr = h ? apr2 : apr;
            const uint32_t soff = (uint32_t)(r * SST + bc8_) * 2;
            const uint32_t sb = sbase + buf * 4 * tilebytes + soff;
            const size_t aoff = (size_t)gr * K + k0 + bc8_;
            cp16(sb, Ahi + aoff);
            cp16(sb + tilebytes, Alo + aoff);
        }
    };
    auto issueB = [&](int buf, int k0) {
#pragma unroll
        for (int h = 0; h < 2; h++) {
            const int r = br_ + h * 64;
            const uint32_t soff = (uint32_t)(r * SST + bc8_) * 2;
            const uint32_t sb = sbase + buf * 4 * tilebytes + 2 * tilebytes + soff;
            const size_t boff = (size_t)(bn + r) * K + k0 + bc8_;
            cp16(sb, Bthi + boff);
            cp16(sb + tilebytes, Btlo + boff);
        }
    };

    const int nch = K >> 5;
    if (presplit) issueA(0, 0); else ldgA(0);
    issueB(0, 0);
    cp_commit();
    if (!presplit) stsA(0);

    int buf = 0;
    for (int t = 0; t < nch; t++) {
        const bool has = (t + 1 < nch);
        if (has) {
            const int k1 = (t + 1) << 5;
            if (presplit) issueA(buf ^ 1, k1); else ldgA(k1);
            issueB(buf ^ 1, k1);
            cp_commit();
            cp_wait<1>();
        } else {
            cp_wait<0>();
        }
        __syncthreads();

        const uint32_t sb = sbase + buf * 4 * tilebytes;
        const uint32_t sAh = sb, sAl = sb + tilebytes;
        const uint32_t sBh = sb + 2 * tilebytes, sBl = sb + 3 * tilebytes;

        const int arow = wm + (lane & 15);
        const int acol_off = (lane & 16) ? 8 : 0;
        const int brow = wn + (lane & 7) + ((lane & 16) ? 8 : 0);
        const int bcol_off = (lane & 8) ? 8 : 0;

#pragma unroll
        for (int ks = 0; ks < 2; ks++) {
            const int kb = ks * 16;
            uint32_t ah[2][4], al[2][4];
#pragma unroll
            for (int mt = 0; mt < 2; mt++) {
                const uint32_t aaddr = (uint32_t)(((arow + mt * 16) * SST) + kb + acol_off) * 2;
                ldmx4(ah[mt], sAh + aaddr);
                ldmx4(al[mt], sAl + aaddr);
            }
#pragma unroll
            for (int p = 0; p < 4; p++) {
                uint32_t bh[4], bl[4];
                const uint32_t baddr = (uint32_t)(((brow + p * 16) * SST) + kb + bcol_off) * 2;
                ldmx4(bh, sBh + baddr);
                ldmx4(bl, sBl + baddr);
#pragma unroll
                for (int sub = 0; sub < 2; sub++) {
                    const int nt = p * 2 + sub;
                    const uint32_t bh0 = bh[sub * 2], bh1 = bh[sub * 2 + 1];
                    const uint32_t bl0 = bl[sub * 2], bl1 = bl[sub * 2 + 1];
#pragma unroll
                    for (int mt = 0; mt < 2; mt++) {
                        mma16816(acc[mt][nt], ah[mt], bh0, bh1);
                        mma16816(acc[mt][nt], ah[mt], bl0, bl1);
                        mma16816(acc[mt][nt], al[mt], bh0, bh1);
                    }
                }
            }
        }
        __syncthreads();
        if (has && !presplit) stsA(buf ^ 1);
        buf ^= 1;
    }

    // ---------------- epilogue ----------------
#pragma unroll
    for (int mt = 0; mt < 2; mt++) {
        const int r0 = bm + wm + mt * 16 + lr;
        const bool ok0 = r0 < M, ok1 = (r0 + 8) < M;
#pragma unroll
        for (int nt = 0; nt < 8; nt++) {
            const int col = bn + wn + nt * 8 + lc;
            float2 v0 = make_float2(acc[mt][nt][0], acc[mt][nt][1]);
            float2 v1 = make_float2(acc[mt][nt][2], acc[mt][nt][3]);
            if (flags & 1) {
                float2 bb = *(const float2*)(bias + col);
                v0.x += bb.x; v0.y += bb.y; v1.x += bb.x; v1.y += bb.y;
            }
            if (flags & 2) {
                v0.x = fmaxf(v0.x, 0.f); v0.y = fmaxf(v0.y, 0.f);
                v1.x = fmaxf(v1.x, 0.f); v1.y = fmaxf(v1.y, 0.f);
            }
            if (ok0) *(float2*)(C + (size_t)r0 * N + col) = v0;
            if (ok1) *(float2*)(C + (size_t)(r0 + 8) * N + col) = v1;
            if (flags & 8) {
                float s0 = (ok0 ? v0.x : 0.f) + (ok1 ? v1.x : 0.f);
                float s1 = (ok0 ? v0.y : 0.f) + (ok1 ? v1.y : 0.f);
                float q0 = (ok0 ? v0.x * v0.x : 0.f) + (ok1 ? v1.x * v1.x : 0.f);
                float q1 = (ok0 ? v0.y * v0.y : 0.f) + (ok1 ? v1.y * v1.y : 0.f);
                const int cc = wn + nt * 8 + lc;
                atomicAdd(&cs[cc], s0); atomicAdd(&cs[cc + 1], s1);
                atomicAdd(&cq[cc], q0); atomicAdd(&cq[cc + 1], q1);
            }
            acc[mt][nt][0] = v0.x; acc[mt][nt][1] = v0.y;
            acc[mt][nt][2] = v1.x; acc[mt][nt][3] = v1.y;
        }
    }
    if (flags & 4) {  // fused ls: CTA's 128 cols = one head (N=512)
        const int head = bn >> 7;
#pragma unroll
        for (int mt = 0; mt < 2; mt++) {
            const int r0 = bm + wm + mt * 16 + lr;
            float p0 = 0.f, p8 = 0.f;
#pragma unroll
            for (int nt = 0; nt < 8; nt++) {
                const int c = wn + nt * 8 + lc;
                const float a0 = a_s[head * 128 + c], a1 = a_s[head * 128 + c + 1];
                p0 += acc[mt][nt][0] * a0 + acc[mt][nt][1] * a1;
                p8 += acc[mt][nt][2] * a0 + acc[mt][nt][3] * a1;
            }
            if (r0 < M)     atomicAdd(&g_ls[r0 * 4 + head], p0);
            if (r0 + 8 < M) atomicAdd(&g_ls[(r0 + 8) * 4 + head], p8);
        }
    }
    if (flags & 8) {
        __syncthreads();
        if (tid < 128) {
            atomicAdd(&g_sum[tid], (double)cs[tid]);
            atomicAdd(&g_sumsq[tid], (double)cq[tid]);
        }
    }
}

// ---------------- BatchNorm ----------------
__global__ void zero_stats_kernel() {
    int c = threadIdx.x;
    g_sum[c] = 0.0; g_sumsq[c] = 0.0;
}

__global__ void bn_params_kernel(const float* __restrict__ gamma,
                                 const float* __restrict__ beta, int M) {
    int c = threadIdx.x;
    double mu = g_sum[c] / M;
    double var = g_sumsq[c] / M - mu * mu;
    float sc = gamma[c] * rsqrtf((float)var + 1e-5f);
    g_scale[c] = sc;
    g_shift[c] = beta[c] - (float)mu * sc;
}

// BN apply; fuse_ld: also g_ld; hi/lo: also bf16 split output
__global__ void bn_apply_kernel(float* __restrict__ h, int M, int fuse_ld,
                                __nv_bfloat16* __restrict__ hi,
                                __nv_bfloat16* __restrict__ lo) {
    int i = blockIdx.x * blockDim.x + threadIdx.x;
    if (i >= M * (CH / 4)) return;
    int c = (i & 31) * 4;
    float4 v = ((float4*)h)[i];
    v.x = v.x * g_scale[c + 0] + g_shift[c + 0];
    v.y = v.y * g_scale[c + 1] + g_shift[c + 1];
    v.z = v.z * g_scale[c + 2] + g_shift[c + 2];
    v.w = v.w * g_scale[c + 3] + g_shift[c + 3];
    ((float4*)h)[i] = v;
    if (hi) {
        __nv_bfloat16 h0 = __float2bfloat16(v.x), h1 = __float2bfloat16(v.y);
        __nv_bfloat16 h2 = __float2bfloat16(v.z), h3 = __float2bfloat16(v.w);
        ((uint32_t*)hi)[2 * i]     = pack_bf2(v.x, v.y);
        ((uint32_t*)hi)[2 * i + 1] = pack_bf2(v.z, v.w);
        ((uint32_t*)lo)[2 * i]     = pack_bf2(v.x - __bfloat162float(h0),
                                              v.y - __bfloat162float(h1));
        ((uint32_t*)lo)[2 * i + 1] = pack_bf2(v.z - __bfloat162float(h2),
                                              v.w - __bfloat162float(h3));
    }
    if (fuse_ld) {
        float4 w0 = ((const float4*)g_wld)[c + 0];
        float4 w1 = ((const float4*)g_wld)[c + 1];
        float4 w2 = ((const float4*)g_wld)[c + 2];
        float4 w3 = ((const float4*)g_wld)[c + 3];
        float p0 = v.x * w0.x + v.y * w1.x + v.z * w2.x + v.w * w3.x;
        float p1 = v.x * w0.y + v.y * w1.y + v.z * w2.y + v.w * w3.y;
        float p2 = v.x * w0.z + v.y * w1.z + v.z * w2.z + v.w * w3.z;
        float p3 = v.x * w0.w + v.y * w1.w + v.z * w2.w + v.w * w3.w;
#pragma unroll
        for (int off = 16; off > 0; off >>= 1) {
            p0 += __shfl_xor_sync(0xffffffffu, p0, off);
            p1 += __shfl_xor_sync(0xffffffffu, p1, off);
            p2 += __shfl_xor_sync(0xffffffffu, p2, off);
            p3 += __shfl_xor_sync(0xffffffffu, p3, off);
        }
        if ((i & 31) == 0) ((float4*)g_ld)[i >> 5] = make_float4(p0, p1, p2, p3);
    }
}

// ---------------- GAT pieces ----------------
__global__ void wld_kernel(const float* __restrict__ Wd, const float* __restrict__ ad) {
    int t = blockIdx.x * blockDim.x + threadIdx.x;
    if (t >= 512) return;
    int k = t >> 2, h = t & 3;
    float s = 0.f;
    for (int c = 0; c < 128; c++)
        s += Wd[(size_t)k * 512 + h * 128 + c] * ad[h * 128 + c];
    g_wld[k * 4 + h] = s;
}

__global__ void gat_init_kernel(int n_dst) {
    int stride = gridDim.x * blockDim.x;
    int start = blockIdx.x * blockDim.x + threadIdx.x;
    for (int i = start; i < n_dst * CH; i += stride) g_agg[i] = 0.f;
    for (int i = start; i < n_dst * 4; i += stride) { g_denom[i] = 0.f; g_ls[i] = 0.f; }
}

// merged pass1+2: p = exp(leaky(ls[s]+ld[d])) * mask ; segment-sum denom
__global__ void gat_edge_kernel(const int* __restrict__ src, const int* __restrict__ dst,
                                int E, int n_loop) {
    int e = blockIdx.x * blockDim.x + threadIdx.x;
    if (e >= E + n_loop) return;
    int s, d; bool mask;
    if (e < E) { s = src[e]; d = dst[e]; mask = (s != d); }
    else       { s = d = e - E; mask = true; }
    float4 a = ((const float4*)g_ls)[s];
    float4 b = ((const float4*)g_ld)[d];
    float p0 = mask ? expf(leaky(a.x + b.x)) : 0.f;
    float p1 = mask ? expf(leaky(a.y + b.y)) : 0.f;
    float p2 = mask ? expf(leaky(a.z + b.z)) : 0.f;
    float p3 = mask ? expf(leaky(a.w + b.w)) : 0.f;
    ((float4*)g_logits)[e] = make_float4(p0, p1, p2, p3);
    atomicAdd(&g_denom[d * 4 + 0], p0);
    atomicAdd(&g_denom[d * 4 + 1], p1);
    atomicAdd(&g_denom[d * 4 + 2], p2);
    atomicAdd(&g_denom[d * 4 + 3], p3);
}

__global__ void gat_pass3_kernel(const int* __restrict__ src, const int* __restrict__ dst,
                                 int E, int n_loop) {
    int w = (blockIdx.x * blockDim.x + threadIdx.x) >> 5;
    int lane = threadIdx.x & 31;
    if (w >= E + n_loop) return;
    int s, d;
    if (w < E) { s = src[w]; d = dst[w]; }
    else       { s = d = w - E; }
    float4 P = ((const float4*)g_logits)[w];
    float4 D = ((const float4*)g_denom)[d];
    float a0 = 0.25f * P.x / (D.x > 0.f ? D.x : 1.f);
    float a1 = 0.25f * P.y / (D.y > 0.f ? D.y : 1.f);
    float a2 = 0.25f * P.z / (D.z > 0.f ? D.z : 1.f);
    float a3 = 0.25f * P.w / (D.w > 0.f ? D.w : 1.f);
    const float4* xr = (const float4*)g_xs + (size_t)s * 128;
    float4 x0 = xr[lane], x1 = xr[32 + lane], x2 = xr[64 + lane], x3 = xr[96 + lane];
    float r0 = a0 * x0.x + a1 * x1.x + a2 * x2.x + a3 * x3.x;
    float r1 = a0 * x0.y + a1 * x1.y + a2 * x2.y + a3 * x3.y;
    float r2 = a0 * x0.z + a1 * x1.z + a2 * x2.z + a3 * x3.z;
    float r3 = a0 * x0.w + a1 * x1.w + a2 * x2.w + a3 * x3.w;
    float* out = g_agg + (size_t)d * CH + lane * 4;
    asm volatile("red.global.add.v4.f32 [%0], {%1, %2, %3, %4};"
                 :: "l"(out), "f"(r0), "f"(r1), "f"(r2), "f"(r3) : "memory");
}

// combine; fuse_ld: also g_ld; hi/lo: bf16 split for next relation's A
__global__ void combine_kernel(float* __restrict__ gene, const float* __restrict__ bias,
                               int fuse_ld, __nv_bfloat16* __restrict__ hi,
                               __nv_bfloat16* __restrict__ lo) {
    int i = blockIdx.x * blockDim.x + threadIdx.x;
    if (i >= NGENE * 32) return;
    int c = (i & 31) * 4;
    float4 v = ((float4*)gene)[i];
    float4 ag = ((const float4*)g_agg)[i];
    v.x += ag.x + bias[c + 0];
    v.y += ag.y + bias[c + 1];
    v.z += ag.z + bias[c + 2];
    v.w += ag.w + bias[c + 3];
    ((float4*)gene)[i] = v;
    if (hi) {
        __nv_bfloat16 h0 = __float2bfloat16(v.x), h1 = __float2bfloat16(v.y);
        __nv_bfloat16 h2 = __float2bfloat16(v.z), h3 = __float2bfloat16(v.w);
        ((uint32_t*)hi)[2 * i]     = pack_bf2(v.x, v.y);
        ((uint32_t*)hi)[2 * i + 1] = pack_bf2(v.z, v.w);
        ((uint32_t*)lo)[2 * i]     = pack_bf2(v.x - __bfloat162float(h0),
                                              v.y - __bfloat162float(h1));
        ((uint32_t*)lo)[2 * i + 1] = pack_bf2(v.z - __bfloat162float(h2),
                                              v.w - __bfloat162float(h3));
    }
    if (fuse_ld) {
        float4 w0 = ((const float4*)g_wld)[c + 0];
        float4 w1 = ((const float4*)g_wld)[c + 1];
        float4 w2 = ((const float4*)g_wld)[c + 2];
        float4 w3 = ((const float4*)g_wld)[c + 3];
        float p0 = v.x * w0.x + v.y * w1.x + v.z * w2.x + v.w * w3.x;
        float p1 = v.x * w0.y + v.y * w1.y + v.z * w2.y + v.w * w3.y;
        float p2 = v.x * w0.z + v.y * w1.z + v.z * w2.z + v.w * w3.z;
        float p3 = v.x * w0.w + v.y * w1.w + v.z * w2.w + v.w * w3.w;
#pragma unroll
        for (int off = 16; off > 0; off >>= 1) {
            p0 += __shfl_xor_sync(0xffffffffu, p0, off);
            p1 += __shfl_xor_sync(0xffffffffu, p1, off);
            p2 += __shfl_xor_sync(0xffffffffu, p2, off);
            p3 += __shfl_xor_sync(0xffffffffu, p3, off);
        }
        if ((i & 31) == 0) ((float4*)g_ld)[i >> 5] = make_float4(p0, p1, p2, p3);
    }
}

// ---------------- launch ----------------
extern "C" void kernel_launch(void* const* d_in, const int* in_sizes, int n_in,
                              void* d_out, int out_size) {
    const float* x_gene = (const float*)d_in[0];
    const float* x_dis  = (const float*)d_in[1];
    const int* e1_src = (const int*)d_in[2];
    const int* e1_dst = (const int*)d_in[3];
    const int* e2_src = (const int*)d_in[4];
    const int* e2_dst = (const int*)d_in[5];
    const float* Wg = (const float*)d_in[6];
    const float* bg = (const float*)d_in[7];
    const float* gg = (const float*)d_in[8];
    const float* betag = (const float*)d_in[9];
    const float* Wd = (const float*)d_in[10];
    const float* bd = (const float*)d_in[11];
    const float* gd = (const float*)d_in[12];
    const float* betad = (const float*)d_in[13];
    const float* W1s = (const float*)d_in[14];
    const float* W1d = (const float*)d_in[15];
    const float* a1s = (const float*)d_in[16];
    const float* a1d = (const float*)d_in[17];
    const float* b1  = (const float*)d_in[18];
    const float* W2s = (const float*)d_in[19];
    const float* W2d = (const float*)d_in[20];
    const float* a2s = (const float*)d_in[21];
    const float* a2d = (const float*)d_in[22];
    const float* b2  = (const float*)d_in[23];

    float* out_gene = (float*)d_out;
    float* out_dis  = (float*)d_out + (size_t)NGENE * CH;

    float* xs_ptr = nullptr;
    cudaGetSymbolAddress((void**)&xs_ptr, g_xs);
    __nv_bfloat16 *ahi, *alo, *bthi, *btlo;
    cudaGetSymbolAddress((void**)&ahi, g_ahi);
    cudaGetSymbolAddress((void**)&alo, g_alo);
    cudaGetSymbolAddress((void**)&bthi, g_bthi);
    cudaGetSymbolAddress((void**)&btlo, g_btlo);

    // ---- encode gene: relu(x@Wg+bg) -> BN (colsum fused into GEMM) ----
    zero_stats_kernel<<<1, 128>>>();
    split_bt_kernel<<<(FGENE * CH + 255) / 256, 256>>>(Wg, bthi, btlo, FGENE, CH);
    gemm_mma_kernel<<<dim3(1, (NGENE + 127) / 128), 256>>>(
        x_gene, nullptr, nullptr, bthi, btlo, bg, nullptr, out_gene, NGENE, CH, FGENE, 1 | 2 | 8);
    bn_params_kernel<<<1, 128>>>(gg, betag, NGENE);
    wld_kernel<<<2, 256>>>(W1d, a1d);                                  // for fused ld
    bn_apply_kernel<<<(NGENE * 32 + 255) / 256, 256>>>(out_gene, NGENE, 1, nullptr, nullptr);

    // ---- encode dis (fused: bf16 split of BN'd dis = rel1 A) ----
    zero_stats_kernel<<<1, 128>>>();
    split_bt_kernel<<<(FDIS * CH + 255) / 256, 256>>>(Wd, bthi, btlo, FDIS, CH);
    gemm_mma_kernel<<<dim3(1, (NDIS + 127) / 128), 256>>>(
        x_dis, nullptr, nullptr, bthi, btlo, bd, nullptr, out_dis, NDIS, CH, FDIS, 1 | 2 | 8);
    bn_params_kernel<<<1, 128>>>(gd, betad, NDIS);
    bn_apply_kernel<<<(NDIS * 32 + 255) / 256, 256>>>(out_dis, NDIS, 0, ahi, alo);

    // ---- relation 1: dis -> gene ----
    {
        const int E = NE, n_loop = NDIS, ET = E + n_loop;
        split_bt_kernel<<<(CH * 512 + 255) / 256, 256>>>(W1s, bthi, btlo, CH, 512);
        gat_init_kernel<<<2048, 256>>>(NGENE);
        gemm_mma_kernel<<<dim3(4, (NDIS + 127) / 128), 256>>>(
            nullptr, ahi, alo, bthi, btlo, nullptr, a1s, xs_ptr, NDIS, 512, CH, 4);
        gat_edge_kernel<<<(ET + 255) / 256, 256>>>(e1_src, e1_dst, E, n_loop);
        gat_pass3_kernel<<<(ET + 7) / 8, 256>>>(e1_src, e1_dst, E, n_loop);
        wld_kernel<<<2, 256>>>(W2d, a2d);                              // for fused ld
        combine_kernel<<<(NGENE * 32 + 255) / 256, 256>>>(out_gene, b1, 1, ahi, alo);
    }

    // ---- relation 2: gene -> gene ----
    {
        const int E = NE, n_loop = NGENE, ET = E + n_loop;
        split_bt_kernel<<<(CH * 512 + 255) / 256, 256>>>(W2s, bthi, btlo, CH, 512);
        gat_init_kernel<<<2048, 256>>>(NGENE);
        gemm_mma_kernel<<<dim3(4, (NGENE + 127) / 128), 256>>>(
            nullptr, ahi, alo, bthi, btlo, nullptr, a2s, xs_ptr, NGENE, 512, CH, 4);
        gat_edge_kernel<<<(ET + 255) / 256, 256>>>(e2_src, e2_dst, E, n_loop);
        gat_pass3_kernel<<<(ET + 7) / 8, 256>>>(e2_src, e2_dst, E, n_loop);
        combine_kernel<<<(NGENE * 32 + 255) / 256, 256>>>(out_gene, b2, 0, nullptr, nullptr);
    }
}

// round 8
// speedup vs baseline: 1.0574x; 1.0574x over previous
#include <cuda_runtime.h>
#include <cuda_bf16.h>
#include <math.h>
#include <cstdint>

#define NGENE 50000
#define NDIS  25000
#define FGENE 512
#define FDIS  256
#define CH    128
#define NE    150000

// ---------------- scratch (static device globals; no allocation) ----------------
__device__ float  g_xs[(size_t)NGENE * 512];
__device__ float  g_agg1[(size_t)NGENE * CH];
__device__ float  g_agg2[(size_t)NGENE * CH];
__device__ float  g_ls1[NGENE * 4];
__device__ float  g_ls2[NGENE * 4];
__device__ float  g_ld1[NGENE * 4];
__device__ float  g_ld2[NGENE * 4];
__device__ float  g_logits1[(NE + NDIS) * 4];
__device__ float  g_logits2[(NE + NGENE) * 4];
__device__ float  g_denom1[NGENE * 4];
__device__ float  g_denom2[NGENE * 4];
__device__ float  g_wld1[512];
__device__ float  g_wld2[512];
__device__ float  g_psG[400 * 128], g_pqG[400 * 128];
__device__ float  g_psD[400 * 128], g_pqD[400 * 128];
__device__ float  g_scaleG[CH], g_shiftG[CH], g_scaleD[CH], g_shiftD[CH];
__device__ __align__(256) __nv_bfloat16 g_btg_hi[512 * 128], g_btg_lo[512 * 128];
__device__ __align__(256) __nv_bfloat16 g_btd_hi[512 * 128], g_btd_lo[512 * 128];
__device__ __align__(256) __nv_bfloat16 g_bt1_hi[512 * 128], g_bt1_lo[512 * 128];
__device__ __align__(256) __nv_bfloat16 g_bt2_hi[512 * 128], g_bt2_lo[512 * 128];

// ---------------- small helpers ----------------
__device__ __forceinline__ float leaky(float x) { return x > 0.f ? x : 0.2f * x; }
__device__ __forceinline__ uint32_t smem_u32(const void* p) {
    uint32_t a;
    asm("{ .reg .u64 t; cvta.to.shared.u64 t, %1; cvt.u32.u64 %0, t; }" : "=r"(a) : "l"(p));
    return a;
}
__device__ __forceinline__ void mma16816(float* c, const uint32_t* a,
                                         uint32_t b0, uint32_t b1) {
    asm volatile("mma.sync.aligned.m16n8k16.row.col.f32.bf16.bf16.f32 "
                 "{%0,%1,%2,%3}, {%4,%5,%6,%7}, {%8,%9}, {%0,%1,%2,%3};"
                 : "+f"(c[0]), "+f"(c[1]), "+f"(c[2]), "+f"(c[3])
                 : "r"(a[0]), "r"(a[1]), "r"(a[2]), "r"(a[3]), "r"(b0), "r"(b1));
}
__device__ __forceinline__ void ldmx4(uint32_t* r, uint32_t addr) {
    asm volatile("ldmatrix.sync.aligned.m8n8.x4.shared.b16 {%0,%1,%2,%3}, [%4];"
                 : "=r"(r[0]), "=r"(r[1]), "=r"(r[2]), "=r"(r[3]) : "r"(addr));
}
__device__ __forceinline__ void cp16(uint32_t saddr, const void* g) {
    asm volatile("cp.async.cg.shared.global [%0], [%1], 16;" :: "r"(saddr), "l"(g));
}
__device__ __forceinline__ void cp_commit() {
    asm volatile("cp.async.commit_group;" ::: "memory");
}
template <int N_>
__device__ __forceinline__ void cp_wait() {
    asm volatile("cp.async.wait_group %0;" :: "n"(N_) : "memory");
}
__device__ __forceinline__ uint32_t pack_bf2(float x, float y) {
    __nv_bfloat162 t(__float2bfloat16(x), __float2bfloat16(y));
    return *(uint32_t*)&t;
}

// B [K,N] fp32 -> Bt hi/lo [N,K] bf16 (transpose; tiny)
__global__ void split_bt_kernel(const float* __restrict__ B,
                                __nv_bfloat16* __restrict__ thi,
                                __nv_bfloat16* __restrict__ tlo, int K, int N) {
    int idx = blockIdx.x * blockDim.x + threadIdx.x;
    if (idx >= K * N) return;
    int k = idx / N, n = idx % N;
    float v = B[idx];
    __nv_bfloat16 h = __float2bfloat16(v);
    thi[(size_t)n * K + k] = h;
    tlo[(size_t)n * K + k] = __float2bfloat16(v - __bfloat162float(h));
}

// ---------------- split-bf16 GEMM: fp32 A (inline split) + bf16 Bt ----------------
// flags: 1=bias, 2=relu, 4=fused ls (-> ls_out), 8=fused colsum partials (-> ps/pq)
#define SST 40

__global__ __launch_bounds__(256, 2)
void gemm_mma_kernel(const float* __restrict__ A,
                     const __nv_bfloat16* __restrict__ Bthi,
                     const __nv_bfloat16* __restrict__ Btlo,
                     const float* __restrict__ bias, const float* __restrict__ a_s,
                     float* __restrict__ ls_out, float* __restrict__ ps,
                     float* __restrict__ pq, float* __restrict__ C,
                     int M, int N, int K, int flags)
{
    __shared__ __align__(16) __nv_bfloat16 smem[2][4][128 * SST];  // Ah, Al, Bh, Bl
    __shared__ float cs[128], cq[128];

    const int tid = threadIdx.x, wid = tid >> 5, lane = tid & 31;
    const int bm = blockIdx.y * 128, bn = blockIdx.x * 128;
    const int wm = (wid & 3) * 32, wn = (wid >> 2) * 64;
    const int lr = lane >> 2, lc = (lane & 3) * 2;
    const uint32_t sbase = smem_u32(&smem[0][0][0]);
    const uint32_t tilebytes = 128 * SST * 2;

    if ((flags & 8) && tid < 128) { cs[tid] = 0.f; cq[tid] = 0.f; }

    float acc[2][8][4];
#pragma unroll
    for (int mt = 0; mt < 2; mt++)
#pragma unroll
        for (int nt = 0; nt < 8; nt++)
#pragma unroll
            for (int j = 0; j < 4; j++) acc[mt][nt][j] = 0.f;

    const int br_ = tid >> 2, bc8_ = (tid & 3) * 8;
    const int ar = tid >> 1, ac = (tid & 1) * 16;
    const int agr = (bm + ar < M) ? (bm + ar) : (M - 1);

    float av[16];

    auto ldgA = [&](int k0) {
        const float4* p = (const float4*)(A + (size_t)agr * K + k0 + ac);
        float4 v0 = p[0], v1 = p[1], v2 = p[2], v3 = p[3];
        av[0] = v0.x; av[1] = v0.y; av[2] = v0.z; av[3] = v0.w;
        av[4] = v1.x; av[5] = v1.y; av[6] = v1.z; av[7] = v1.w;
        av[8] = v2.x; av[9] = v2.y; av[10] = v2.z; av[11] = v2.w;
        av[12] = v3.x; av[13] = v3.y; av[14] = v3.z; av[15] = v3.w;
    };
    auto stsA = [&](int buf) {
        uint32_t hi[8], lo[8];
#pragma unroll
        for (int j = 0; j < 8; j++) {
            float x0 = av[2 * j], x1 = av[2 * j + 1];
            __nv_bfloat16 h0 = __float2bfloat16(x0), h1 = __float2bfloat16(x1);
            hi[j] = pack_bf2(x0, x1);
            lo[j] = pack_bf2(x0 - __bfloat162float(h0), x1 - __bfloat162float(h1));
        }
        char* base = (char*)&smem[buf][0][0];
        const uint32_t off = (uint32_t)(ar * SST + ac) * 2;
        *(uint4*)(base + off)      = make_uint4(hi[0], hi[1], hi[2], hi[3]);
        *(uint4*)(base + off + 16) = make_uint4(hi[4], hi[5], hi[6], hi[7]);
        char* basel = (char*)&smem[buf][1][0];
        *(uint4*)(basel + off)      = make_uint4(lo[0], lo[1], lo[2], lo[3]);
        *(uint4*)(basel + off + 16) = make_uint4(lo[4], lo[5], lo[6], lo[7]);
    };
    auto issueB = [&](int buf, int k0) {
#pragma unroll
        for (int h = 0; h < 2; h++) {
            const int r = br_ + h * 64;
            const uint32_t soff = (uint32_t)(r * SST + bc8_) * 2;
            const uint32_t sb = sbase + buf * 4 * tilebytes + 2 * tilebytes + soff;
            const size_t boff = (size_t)(bn + r) * K + k0 + bc8_;
            cp16(sb, Bthi + boff);
            cp16(sb + tilebytes, Btlo + boff);
        }
        cp_commit();
    };

    const int nch = K >> 5;
    ldgA(0); issueB(0, 0); stsA(0);

    int buf = 0;
    for (int t = 0; t < nch; t++) {
        const bool has = (t + 1 < nch);
        if (has) {
            ldgA((t + 1) << 5);
            issueB(buf ^ 1, (t + 1) << 5);
            cp_wait<1>();
        } else {
            cp_wait<0>();
        }
        __syncthreads();

        const uint32_t sb = sbase + buf * 4 * tilebytes;
        const uint32_t sAh = sb, sAl = sb + tilebytes;
        const uint32_t sBh = sb + 2 * tilebytes, sBl = sb + 3 * tilebytes;

        const int arow = wm + (lane & 15);
        const int acol_off = (lane & 16) ? 8 : 0;
        const int brow = wn + (lane & 7) + ((lane & 16) ? 8 : 0);
        const int bcol_off = (lane & 8) ? 8 : 0;

#pragma unroll
        for (int ks = 0; ks < 2; ks++) {
            const int kb = ks * 16;
            uint32_t ah[2][4], al[2][4];
#pragma unroll
            for (int mt = 0; mt < 2; mt++) {
                const uint32_t aaddr = (uint32_t)(((arow + mt * 16) * SST) + kb + acol_off) * 2;
                ldmx4(ah[mt], sAh + aaddr);
                ldmx4(al[mt], sAl + aaddr);
            }
#pragma unroll
            for (int p = 0; p < 4; p++) {
                uint32_t bh[4], bl[4];
                const uint32_t baddr = (uint32_t)(((brow + p * 16) * SST) + kb + bcol_off) * 2;
                ldmx4(bh, sBh + baddr);
                ldmx4(bl, sBl + baddr);
#pragma unroll
                for (int sub = 0; sub < 2; sub++) {
                    const int nt = p * 2 + sub;
                    const uint32_t bh0 = bh[sub * 2], bh1 = bh[sub * 2 + 1];
                    const uint32_t bl0 = bl[sub * 2], bl1 = bl[sub * 2 + 1];
#pragma unroll
                    for (int mt = 0; mt < 2; mt++) {
                        mma16816(acc[mt][nt], ah[mt], bh0, bh1);
                        mma16816(acc[mt][nt], ah[mt], bl0, bl1);
                        mma16816(acc[mt][nt], al[mt], bh0, bh1);
                    }
                }
            }
        }
        __syncthreads();
        if (has) stsA(buf ^ 1);
        buf ^= 1;
    }

    // ---------------- epilogue ----------------
#pragma unroll
    for (int mt = 0; mt < 2; mt++) {
        const int r0 = bm + wm + mt * 16 + lr;
        const bool ok0 = r0 < M, ok1 = (r0 + 8) < M;
#pragma unroll
        for (int nt = 0; nt < 8; nt++) {
            const int col = bn + wn + nt * 8 + lc;
            float2 v0 = make_float2(acc[mt][nt][0], acc[mt][nt][1]);
            float2 v1 = make_float2(acc[mt][nt][2], acc[mt][nt][3]);
            if (flags & 1) {
                float2 bb = *(const float2*)(bias + col);
                v0.x += bb.x; v0.y += bb.y; v1.x += bb.x; v1.y += bb.y;
            }
            if (flags & 2) {
                v0.x = fmaxf(v0.x, 0.f); v0.y = fmaxf(v0.y, 0.f);
                v1.x = fmaxf(v1.x, 0.f); v1.y = fmaxf(v1.y, 0.f);
            }
            if (ok0) *(float2*)(C + (size_t)r0 * N + col) = v0;
            if (ok1) *(float2*)(C + (size_t)(r0 + 8) * N + col) = v1;
            if (flags & 8) {
                float s0 = (ok0 ? v0.x : 0.f) + (ok1 ? v1.x : 0.f);
                float s1 = (ok0 ? v0.y : 0.f) + (ok1 ? v1.y : 0.f);
                float q0 = (ok0 ? v0.x * v0.x : 0.f) + (ok1 ? v1.x * v1.x : 0.f);
                float q1 = (ok0 ? v0.y * v0.y : 0.f) + (ok1 ? v1.y * v1.y : 0.f);
                const int cc = wn + nt * 8 + lc;
                atomicAdd(&cs[cc], s0); atomicAdd(&cs[cc + 1], s1);
                atomicAdd(&cq[cc], q0); atomicAdd(&cq[cc + 1], q1);
            }
            acc[mt][nt][0] = v0.x; acc[mt][nt][1] = v0.y;
            acc[mt][nt][2] = v1.x; acc[mt][nt][3] = v1.y;
        }
    }
    if (flags & 4) {  // fused ls: CTA's 128 cols = one head (N=512)
        const int head = bn >> 7;
#pragma unroll
        for (int mt = 0; mt < 2; mt++) {
            const int r0 = bm + wm + mt * 16 + lr;
            float p0 = 0.f, p8 = 0.f;
#pragma unroll
            for (int nt = 0; nt < 8; nt++) {
                const int c = wn + nt * 8 + lc;
                const float a0 = a_s[head * 128 + c], a1 = a_s[head * 128 + c + 1];
                p0 += acc[mt][nt][0] * a0 + acc[mt][nt][1] * a1;
                p8 += acc[mt][nt][2] * a0 + acc[mt][nt][3] * a1;
            }
            if (r0 < M)     atomicAdd(&ls_out[r0 * 4 + head], p0);
            if (r0 + 8 < M) atomicAdd(&ls_out[(r0 + 8) * 4 + head], p8);
        }
    }
    if (flags & 8) {
        __syncthreads();
        if (tid < 128) {
            ps[blockIdx.y * 128 + tid] = cs[tid];
            pq[blockIdx.y * 128 + tid] = cq[tid];
        }
    }
}

// ---------------- BatchNorm ----------------
__global__ void bn_params_kernel(const float* __restrict__ gamma,
                                 const float* __restrict__ beta,
                                 const float* __restrict__ ps,
                                 const float* __restrict__ pq,
                                 int nb, int M,
                                 float* __restrict__ scale, float* __restrict__ shift) {
    int c = threadIdx.x;
    double s = 0.0, q = 0.0;
    for (int b = 0; b < nb; b++) { s += ps[b * 128 + c]; q += pq[b * 128 + c]; }
    double mu = s / M;
    double var = q / M - mu * mu;
    float sc = gamma[c] * rsqrtf((float)var + 1e-5f);
    scale[c] = sc;
    shift[c] = beta[c] - (float)mu * sc;
}

// BN apply; wld!=null: also compute ld_out (warp-per-row reduce)
__global__ void bn_apply_kernel(float* __restrict__ h, int M,
                                const float* __restrict__ scale,
                                const float* __restrict__ shift,
                                const float* __restrict__ wld,
                                float* __restrict__ ld_out) {
    int i = blockIdx.x * blockDim.x + threadIdx.x;
    if (i >= M * (CH / 4)) return;
    int c = (i & 31) * 4;
    float4 v = ((float4*)h)[i];
    v.x = v.x * scale[c + 0] + shift[c + 0];
    v.y = v.y * scale[c + 1] + shift[c + 1];
    v.z = v.z * scale[c + 2] + shift[c + 2];
    v.w = v.w * scale[c + 3] + shift[c + 3];
    ((float4*)h)[i] = v;
    if (wld) {
        float4 w0 = ((const float4*)wld)[c + 0];
        float4 w1 = ((const float4*)wld)[c + 1];
        float4 w2 = ((const float4*)wld)[c + 2];
        float4 w3 = ((const float4*)wld)[c + 3];
        float p0 = v.x * w0.x + v.y * w1.x + v.z * w2.x + v.w * w3.x;
        float p1 = v.x * w0.y + v.y * w1.y + v.z * w2.y + v.w * w3.y;
        float p2 = v.x * w0.z + v.y * w1.z + v.z * w2.z + v.w * w3.z;
        float p3 = v.x * w0.w + v.y * w1.w + v.z * w2.w + v.w * w3.w;
#pragma unroll
        for (int off = 16; off > 0; off >>= 1) {
            p0 += __shfl_xor_sync(0xffffffffu, p0, off);
            p1 += __shfl_xor_sync(0xffffffffu, p1, off);
            p2 += __shfl_xor_sync(0xffffffffu, p2, off);
            p3 += __shfl_xor_sync(0xffffffffu, p3, off);
        }
        if ((i & 31) == 0) ((float4*)ld_out)[i >> 5] = make_float4(p0, p1, p2, p3);
    }
}

// ---------------- GAT pieces ----------------
__global__ void wld_kernel(const float* __restrict__ Wd, const float* __restrict__ ad,
                           float* __restrict__ out) {
    int t = blockIdx.x * blockDim.x + threadIdx.x;
    if (t >= 512) return;
    int k = t >> 2, h = t & 3;
    float s = 0.f;
    for (int c = 0; c < 128; c++)
        s += Wd[(size_t)k * 512 + h * 128 + c] * ad[h * 128 + c];
    out[k * 4 + h] = s;
}

__global__ void gat_init_kernel(float* __restrict__ agg, float* __restrict__ denom,
                                float* __restrict__ ls, int n) {
    int stride = gridDim.x * blockDim.x;
    int start = blockIdx.x * blockDim.x + threadIdx.x;
    float4 z = make_float4(0.f, 0.f, 0.f, 0.f);
    for (int i = start; i < n * 32; i += stride) ((float4*)agg)[i] = z;
    for (int i = start; i < n; i += stride) {
        ((float4*)denom)[i] = z; ((float4*)ls)[i] = z;
    }
}

// merged softmax-numerator + denom pass
__global__ void gat_edge_kernel(const int* __restrict__ src, const int* __restrict__ dst,
                                const float* __restrict__ ls, const float* __restrict__ ld,
                                float* __restrict__ denom, float* __restrict__ logits,
                                int E, int n_loop) {
    int e = blockIdx.x * blockDim.x + threadIdx.x;
    if (e >= E + n_loop) return;
    int s, d; bool mask;
    if (e < E) { s = src[e]; d = dst[e]; mask = (s != d); }
    else       { s = d = e - E; mask = true; }
    float4 a = ((const float4*)ls)[s];
    float4 b = ((const float4*)ld)[d];
    float p0 = mask ? expf(leaky(a.x + b.x)) : 0.f;
    float p1 = mask ? expf(leaky(a.y + b.y)) : 0.f;
    float p2 = mask ? expf(leaky(a.z + b.z)) : 0.f;
    float p3 = mask ? expf(leaky(a.w + b.w)) : 0.f;
    ((float4*)logits)[e] = make_float4(p0, p1, p2, p3);
    atomicAdd(&denom[d * 4 + 0], p0);
    atomicAdd(&denom[d * 4 + 1], p1);
    atomicAdd(&denom[d * 4 + 2], p2);
    atomicAdd(&denom[d * 4 + 3], p3);
}

__global__ void gat_pass3_kernel(const int* __restrict__ src, const int* __restrict__ dst,
                                 const float* __restrict__ logits,
                                 const float* __restrict__ denom,
                                 float* __restrict__ agg, int E, int n_loop) {
    int w = (blockIdx.x * blockDim.x + threadIdx.x) >> 5;
    int lane = threadIdx.x & 31;
    if (w >= E + n_loop) return;
    int s, d;
    if (w < E) { s = src[w]; d = dst[w]; }
    else       { s = d = w - E; }
    float4 P = ((const float4*)logits)[w];
    float4 D = ((const float4*)denom)[d];
    float a0 = 0.25f * P.x / (D.x > 0.f ? D.x : 1.f);
    float a1 = 0.25f * P.y / (D.y > 0.f ? D.y : 1.f);
    float a2 = 0.25f * P.z / (D.z > 0.f ? D.z : 1.f);
    float a3 = 0.25f * P.w / (D.w > 0.f ? D.w : 1.f);
    const float4* xr = (const float4*)g_xs + (size_t)s * 128;
    float4 x0 = xr[lane], x1 = xr[32 + lane], x2 = xr[64 + lane], x3 = xr[96 + lane];
    float r0 = a0 * x0.x + a1 * x1.x + a2 * x2.x + a3 * x3.x;
    float r1 = a0 * x0.y + a1 * x1.y + a2 * x2.y + a3 * x3.y;
    float r2 = a0 * x0.z + a1 * x1.z + a2 * x2.z + a3 * x3.z;
    float r3 = a0 * x0.w + a1 * x1.w + a2 * x2.w + a3 * x3.w;
    float* out = agg + (size_t)d * CH + lane * 4;
    asm volatile("red.global.add.v4.f32 [%0], {%1, %2, %3, %4};"
                 :: "l"(out), "f"(r0), "f"(r1), "f"(r2), "f"(r3) : "memory");
}

// combine; wld!=null: also compute ld_out for next relation
__global__ void combine_kernel(float* __restrict__ gene, const float* __restrict__ bias,
                               const float* __restrict__ agg,
                               const float* __restrict__ wld, float* __restrict__ ld_out) {
    int i = blockIdx.x * blockDim.x + threadIdx.x;
    if (i >= NGENE * 32) return;
    int c = (i & 31) * 4;
    float4 v = ((float4*)gene)[i];
    float4 ag = ((const float4*)agg)[i];
    v.x += ag.x + bias[c + 0];
    v.y += ag.y + bias[c + 1];
    v.z += ag.z + bias[c + 2];
    v.w += ag.w + bias[c + 3];
    ((float4*)gene)[i] = v;
    if (wld) {
        float4 w0 = ((const float4*)wld)[c + 0];
        float4 w1 = ((const float4*)wld)[c + 1];
        float4 w2 = ((const float4*)wld)[c + 2];
        float4 w3 = ((const float4*)wld)[c + 3];
        float p0 = v.x * w0.x + v.y * w1.x + v.z * w2.x + v.w * w3.x;
        float p1 = v.x * w0.y + v.y * w1.y + v.z * w2.y + v.w * w3.y;
        float p2 = v.x * w0.z + v.y * w1.z + v.z * w2.z + v.w * w3.z;
        float p3 = v.x * w0.w + v.y * w1.w + v.z * w2.w + v.w * w3.w;
#pragma unroll
        for (int off = 16; off > 0; off >>= 1) {
            p0 += __shfl_xor_sync(0xffffffffu, p0, off);
            p1 += __shfl_xor_sync(0xffffffffu, p1, off);
            p2 += __shfl_xor_sync(0xffffffffu, p2, off);
            p3 += __shfl_xor_sync(0xffffffffu, p3, off);
        }
        if ((i & 31) == 0) ((float4*)ld_out)[i >> 5] = make_float4(p0, p1, p2, p3);
    }
}

// ---------------- launch ----------------
#define SYM(p, s) cudaGetSymbolAddress((void**)&p, s)

extern "C" void kernel_launch(void* const* d_in, const int* in_sizes, int n_in,
                              void* d_out, int out_size) {
    const float* x_gene = (const float*)d_in[0];
    const float* x_dis  = (const float*)d_in[1];
    const int* e1_src = (const int*)d_in[2];
    const int* e1_dst = (const int*)d_in[3];
    const int* e2_src = (const int*)d_in[4];
    const int* e2_dst = (const int*)d_in[5];
    const float* Wg = (const float*)d_in[6];
    const float* bg = (const float*)d_in[7];
    const float* gg = (const float*)d_in[8];
    const float* betag = (const float*)d_in[9];
    const float* Wd = (const float*)d_in[10];
    const float* bd = (const float*)d_in[11];
    const float* gd = (const float*)d_in[12];
    const float* betad = (const float*)d_in[13];
    const float* W1s = (const float*)d_in[14];
    const float* W1d = (const float*)d_in[15];
    const float* a1s = (const float*)d_in[16];
    const float* a1d = (const float*)d_in[17];
    const float* b1  = (const float*)d_in[18];
    const float* W2s = (const float*)d_in[19];
    const float* W2d = (const float*)d_in[20];
    const float* a2s = (const float*)d_in[21];
    const float* a2d = (const float*)d_in[22];
    const float* b2  = (const float*)d_in[23];

    float* out_gene = (float*)d_out;
    float* out_dis  = (float*)d_out + (size_t)NGENE * CH;

    float *xs, *agg1, *agg2, *ls1, *ls2, *ld1, *ld2, *lg1, *lg2, *dn1, *dn2;
    float *wld1, *wld2, *psG, *pqG, *psD, *pqD, *scG, *shG, *scD, *shD;
    __nv_bfloat16 *btg_h, *btg_l, *btd_h, *btd_l, *bt1_h, *bt1_l, *bt2_h, *bt2_l;
    SYM(xs, g_xs); SYM(agg1, g_agg1); SYM(agg2, g_agg2);
    SYM(ls1, g_ls1); SYM(ls2, g_ls2); SYM(ld1, g_ld1); SYM(ld2, g_ld2);
    SYM(lg1, g_logits1); SYM(lg2, g_logits2); SYM(dn1, g_denom1); SYM(dn2, g_denom2);
    SYM(wld1, g_wld1); SYM(wld2, g_wld2);
    SYM(psG, g_psG); SYM(pqG, g_pqG); SYM(psD, g_psD); SYM(pqD, g_pqD);
    SYM(scG, g_scaleG); SYM(shG, g_shiftG); SYM(scD, g_scaleD); SYM(shD, g_shiftD);
    SYM(btg_h, g_btg_hi); SYM(btg_l, g_btg_lo); SYM(btd_h, g_btd_hi); SYM(btd_l, g_btd_lo);
    SYM(bt1_h, g_bt1_hi); SYM(bt1_l, g_bt1_lo); SYM(bt2_h, g_bt2_hi); SYM(bt2_l, g_bt2_lo);

    cudaStream_t s1, s2;
    cudaStreamCreateWithFlags(&s1, cudaStreamNonBlocking);
    cudaStreamCreateWithFlags(&s2, cudaStreamNonBlocking);
    cudaEvent_t e0, e_wld1, e_init1, e_xs1, e_misc2;
    cudaEventCreateWithFlags(&e0, cudaEventDisableTiming);
    cudaEventCreateWithFlags(&e_wld1, cudaEventDisableTiming);
    cudaEventCreateWithFlags(&e_init1, cudaEventDisableTiming);
    cudaEventCreateWithFlags(&e_xs1, cudaEventDisableTiming);
    cudaEventCreateWithFlags(&e_misc2, cudaEventDisableTiming);

    cudaEventRecord(e0, 0);
    cudaStreamWaitEvent(s1, e0, 0);
    cudaStreamWaitEvent(s2, e0, 0);

    const int GY_G = (NGENE + 127) / 128;   // 391
    const int GY_D = (NDIS + 127) / 128;    // 196

    // ---- s2: misc small kernels ----
    wld_kernel<<<2, 256, 0, s2>>>(W1d, a1d, wld1);
    cudaEventRecord(e_wld1, s2);
    gat_init_kernel<<<1024, 256, 0, s2>>>(agg1, dn1, ls1, NGENE);
    cudaEventRecord(e_init1, s2);
    gat_init_kernel<<<1024, 256, 0, s2>>>(agg2, dn2, ls2, NGENE);
    wld_kernel<<<2, 256, 0, s2>>>(W2d, a2d, wld2);
    split_bt_kernel<<<(CH * 512 + 255) / 256, 256, 0, s2>>>(W2s, bt2_h, bt2_l, CH, 512);
    cudaEventRecord(e_misc2, s2);

    // ---- s1: dis encode + xs1 GEMM ----
    split_bt_kernel<<<(FDIS * CH + 255) / 256, 256, 0, s1>>>(Wd, btd_h, btd_l, FDIS, CH);
    gemm_mma_kernel<<<dim3(1, GY_D), 256, 0, s1>>>(
        x_dis, btd_h, btd_l, bd, nullptr, nullptr, psD, pqD, out_dis, NDIS, CH, FDIS, 1 | 2 | 8);
    bn_params_kernel<<<1, 128, 0, s1>>>(gd, betad, psD, pqD, GY_D, NDIS, scD, shD);
    bn_apply_kernel<<<(NDIS * 32 + 255) / 256, 256, 0, s1>>>(out_dis, NDIS, scD, shD,
                                                             nullptr, nullptr);
    split_bt_kernel<<<(CH * 512 + 255) / 256, 256, 0, s1>>>(W1s, bt1_h, bt1_l, CH, 512);
    cudaStreamWaitEvent(s1, e_init1, 0);
    gemm_mma_kernel<<<dim3(4, GY_D), 256, 0, s1>>>(
        out_dis, bt1_h, bt1_l, nullptr, a1s, ls1, nullptr, nullptr, xs, NDIS, 512, CH, 4);
    cudaEventRecord(e_xs1, s1);

    // ---- s0: gene encode ----
    split_bt_kernel<<<(FGENE * CH + 255) / 256, 256>>>(Wg, btg_h, btg_l, FGENE, CH);
    gemm_mma_kernel<<<dim3(1, GY_G), 256>>>(
        x_gene, btg_h, btg_l, bg, nullptr, nullptr, psG, pqG, out_gene, NGENE, CH, FGENE, 1 | 2 | 8);
    bn_params_kernel<<<1, 128>>>(gg, betag, psG, pqG, GY_G, NGENE, scG, shG);
    cudaStreamWaitEvent(0, e_wld1, 0);
    bn_apply_kernel<<<(NGENE * 32 + 255) / 256, 256>>>(out_gene, NGENE, scG, shG, wld1, ld1);

    // ---- relation 1 on s0 ----
    cudaStreamWaitEvent(0, e_xs1, 0);
    {
        const int E = NE, n_loop = NDIS, ET = E + n_loop;
        gat_edge_kernel<<<(ET + 255) / 256, 256>>>(e1_src, e1_dst, ls1, ld1, dn1, lg1, E, n_loop);
        gat_pass3_kernel<<<(ET + 7) / 8, 256>>>(e1_src, e1_dst, lg1, dn1, agg1, E, n_loop);
    }
    cudaStreamWaitEvent(0, e_misc2, 0);
    combine_kernel<<<(NGENE * 32 + 255) / 256, 256>>>(out_gene, b1, agg1, wld2, ld2);

    // ---- relation 2 on s0 ----
    gemm_mma_kernel<<<dim3(4, GY_G), 256>>>(
        out_gene, bt2_h, bt2_l, nullptr, a2s, ls2, nullptr, nullptr, xs, NGENE, 512, CH, 4);
    {
        const int E = NE, n_loop = NGENE, ET = E + n_loop;
        gat_edge_kernel<<<(ET + 255) / 256, 256>>>(e2_src, e2_dst, ls2, ld2, dn2, lg2, E, n_loop);
        gat_pass3_kernel<<<(ET + 7) / 8, 256>>>(e2_src, e2_dst, lg2, dn2, agg2, E, n_loop);
    }
    combine_kernel<<<(NGENE * 32 + 255) / 256, 256>>>(out_gene, b2, agg2, nullptr, nullptr);

    cudaEventDestroy(e0);
    cudaEventDestroy(e_wld1);
    cudaEventDestroy(e_init1);
    cudaEventDestroy(e_xs1);
    cudaEventDestroy(e_misc2);
    cudaStreamDestroy(s1);
    cudaStreamDestroy(s2);
}

// round 9
// speedup vs baseline: 1.1729x; 1.1092x over previous
#include <cuda_runtime.h>
#include <cuda_bf16.h>
#include <math.h>
#include <cstdint>

#define NGENE 50000
#define NDIS  25000
#define FGENE 512
#define FDIS  256
#define CH    128
#define NE    150000

// ---------------- scratch (static device globals; no allocation) ----------------
__device__ float  g_xs[(size_t)NGENE * 512];
__device__ float  g_agg1[(size_t)NGENE * CH];
__device__ float  g_agg2[(size_t)NGENE * CH];
__device__ float  g_ls1[NGENE * 4];
__device__ float  g_ls2[NGENE * 4];
__device__ float  g_ld1[NGENE * 4];
__device__ float  g_ld2[NGENE * 4];
__device__ float  g_logits1[(NE + NDIS) * 4];
__device__ float  g_logits2[(NE + NGENE) * 4];
__device__ float  g_denom1[NGENE * 4];
__device__ float  g_denom2[NGENE * 4];
__device__ float  g_wld1[512];
__device__ float  g_wld2[512];
__device__ float  g_psG[400 * 128], g_pqG[400 * 128];
__device__ float  g_psD[400 * 128], g_pqD[400 * 128];
__device__ float  g_scaleG[CH], g_shiftG[CH], g_scaleD[CH], g_shiftD[CH];
__device__ __align__(256) __nv_bfloat16 g_btg_hi[512 * 128], g_btg_lo[512 * 128];
__device__ __align__(256) __nv_bfloat16 g_btd_hi[512 * 128], g_btd_lo[512 * 128];
__device__ __align__(256) __nv_bfloat16 g_bt1_hi[512 * 128], g_bt1_lo[512 * 128];
__device__ __align__(256) __nv_bfloat16 g_bt2_hi[512 * 128], g_bt2_lo[512 * 128];

// ---------------- small helpers ----------------
__device__ __forceinline__ float leaky(float x) { return x > 0.f ? x : 0.2f * x; }
__device__ __forceinline__ uint32_t smem_u32(const void* p) {
    uint32_t a;
    asm("{ .reg .u64 t; cvta.to.shared.u64 t, %1; cvt.u32.u64 %0, t; }" : "=r"(a) : "l"(p));
    return a;
}
__device__ __forceinline__ void mma16816(float* c, const uint32_t* a,
                                         uint32_t b0, uint32_t b1) {
    asm volatile("mma.sync.aligned.m16n8k16.row.col.f32.bf16.bf16.f32 "
                 "{%0,%1,%2,%3}, {%4,%5,%6,%7}, {%8,%9}, {%0,%1,%2,%3};"
                 : "+f"(c[0]), "+f"(c[1]), "+f"(c[2]), "+f"(c[3])
                 : "r"(a[0]), "r"(a[1]), "r"(a[2]), "r"(a[3]), "r"(b0), "r"(b1));
}
__device__ __forceinline__ void ldmx4(uint32_t* r, uint32_t addr) {
    asm volatile("ldmatrix.sync.aligned.m8n8.x4.shared.b16 {%0,%1,%2,%3}, [%4];"
                 : "=r"(r[0]), "=r"(r[1]), "=r"(r[2]), "=r"(r[3]) : "r"(addr));
}
__device__ __forceinline__ void cp16(uint32_t saddr, const void* g) {
    asm volatile("cp.async.cg.shared.global [%0], [%1], 16;" :: "r"(saddr), "l"(g));
}
__device__ __forceinline__ void cp_commit() {
    asm volatile("cp.async.commit_group;" ::: "memory");
}
template <int N_>
__device__ __forceinline__ void cp_wait() {
    asm volatile("cp.async.wait_group %0;" :: "n"(N_) : "memory");
}
__device__ __forceinline__ uint32_t pack_bf2(float x, float y) {
    __nv_bfloat162 t(__float2bfloat16(x), __float2bfloat16(y));
    return *(uint32_t*)&t;
}

// B [K,N] fp32 -> Bt hi/lo [N,K] bf16 (transpose; tiny)
__global__ void split_bt_kernel(const float* __restrict__ B,
                                __nv_bfloat16* __restrict__ thi,
                                __nv_bfloat16* __restrict__ tlo, int K, int N) {
    int idx = blockIdx.x * blockDim.x + threadIdx.x;
    if (idx >= K * N) return;
    int k = idx / N, n = idx % N;
    float v = B[idx];
    __nv_bfloat16 h = __float2bfloat16(v);
    thi[(size_t)n * K + k] = h;
    tlo[(size_t)n * K + k] = __float2bfloat16(v - __bfloat162float(h));
}

// ---------------- split-bf16 GEMM: fp32 A (inline split) + bf16 Bt ----------------
// flags: 1=bias, 2=relu, 4=fused ls (exclusive store -> ls_out), 8=colsum partials
#define SST 40

__global__ __launch_bounds__(256, 2)
void gemm_mma_kernel(const float* __restrict__ A,
                     const __nv_bfloat16* __restrict__ Bthi,
                     const __nv_bfloat16* __restrict__ Btlo,
                     const float* __restrict__ bias, const float* __restrict__ a_s,
                     float* __restrict__ ls_out, float* __restrict__ ps,
                     float* __restrict__ pq, float* __restrict__ C,
                     int M, int N, int K, int flags)
{
    __shared__ __align__(16) __nv_bfloat16 smem[2][4][128 * SST];  // Ah, Al, Bh, Bl
    __shared__ float cs[128], cq[128], sls[128];

    const int tid = threadIdx.x, wid = tid >> 5, lane = tid & 31;
    const int bm = blockIdx.y * 128, bn = blockIdx.x * 128;
    const int wm = (wid & 3) * 32, wn = (wid >> 2) * 64;
    const int lr = lane >> 2, lc = (lane & 3) * 2;
    const uint32_t sbase = smem_u32(&smem[0][0][0]);
    const uint32_t tilebytes = 128 * SST * 2;

    if (tid < 128) {
        if (flags & 8) { cs[tid] = 0.f; cq[tid] = 0.f; }
        if (flags & 4) sls[tid] = 0.f;
    }

    float acc[2][8][4];
#pragma unroll
    for (int mt = 0; mt < 2; mt++)
#pragma unroll
        for (int nt = 0; nt < 8; nt++)
#pragma unroll
            for (int j = 0; j < 4; j++) acc[mt][nt][j] = 0.f;

    const int br_ = tid >> 2, bc8_ = (tid & 3) * 8;
    const int ar = tid >> 1, ac = (tid & 1) * 16;
    const int agr = (bm + ar < M) ? (bm + ar) : (M - 1);

    float av[16];

    auto ldgA = [&](int k0) {
        const float4* p = (const float4*)(A + (size_t)agr * K + k0 + ac);
        float4 v0 = p[0], v1 = p[1], v2 = p[2], v3 = p[3];
        av[0] = v0.x; av[1] = v0.y; av[2] = v0.z; av[3] = v0.w;
        av[4] = v1.x; av[5] = v1.y; av[6] = v1.z; av[7] = v1.w;
        av[8] = v2.x; av[9] = v2.y; av[10] = v2.z; av[11] = v2.w;
        av[12] = v3.x; av[13] = v3.y; av[14] = v3.z; av[15] = v3.w;
    };
    auto stsA = [&](int buf) {
        uint32_t hi[8], lo[8];
#pragma unroll
        for (int j = 0; j < 8; j++) {
            float x0 = av[2 * j], x1 = av[2 * j + 1];
            __nv_bfloat16 h0 = __float2bfloat16(x0), h1 = __float2bfloat16(x1);
            hi[j] = pack_bf2(x0, x1);
            lo[j] = pack_bf2(x0 - __bfloat162float(h0), x1 - __bfloat162float(h1));
        }
        char* base = (char*)&smem[buf][0][0];
        const uint32_t off = (uint32_t)(ar * SST + ac) * 2;
        *(uint4*)(base + off)      = make_uint4(hi[0], hi[1], hi[2], hi[3]);
        *(uint4*)(base + off + 16) = make_uint4(hi[4], hi[5], hi[6], hi[7]);
        char* basel = (char*)&smem[buf][1][0];
        *(uint4*)(basel + off)      = make_uint4(lo[0], lo[1], lo[2], lo[3]);
        *(uint4*)(basel + off + 16) = make_uint4(lo[4], lo[5], lo[6], lo[7]);
    };
    auto issueB = [&](int buf, int k0) {
#pragma unroll
        for (int h = 0; h < 2; h++) {
            const int r = br_ + h * 64;
            const uint32_t soff = (uint32_t)(r * SST + bc8_) * 2;
            const uint32_t sb = sbase + buf * 4 * tilebytes + 2 * tilebytes + soff;
            const size_t boff = (size_t)(bn + r) * K + k0 + bc8_;
            cp16(sb, Bthi + boff);
            cp16(sb + tilebytes, Btlo + boff);
        }
        cp_commit();
    };

    const int nch = K >> 5;
    ldgA(0); issueB(0, 0); stsA(0);

    int buf = 0;
    for (int t = 0; t < nch; t++) {
        const bool has = (t + 1 < nch);
        if (has) {
            ldgA((t + 1) << 5);
            issueB(buf ^ 1, (t + 1) << 5);
            cp_wait<1>();
        } else {
            cp_wait<0>();
        }
        __syncthreads();

        const uint32_t sb = sbase + buf * 4 * tilebytes;
        const uint32_t sAh = sb, sAl = sb + tilebytes;
        const uint32_t sBh = sb + 2 * tilebytes, sBl = sb + 3 * tilebytes;

        const int arow = wm + (lane & 15);
        const int acol_off = (lane & 16) ? 8 : 0;
        const int brow = wn + (lane & 7) + ((lane & 16) ? 8 : 0);
        const int bcol_off = (lane & 8) ? 8 : 0;

#pragma unroll
        for (int ks = 0; ks < 2; ks++) {
            const int kb = ks * 16;
            uint32_t ah[2][4], al[2][4];
#pragma unroll
            for (int mt = 0; mt < 2; mt++) {
                const uint32_t aaddr = (uint32_t)(((arow + mt * 16) * SST) + kb + acol_off) * 2;
                ldmx4(ah[mt], sAh + aaddr);
                ldmx4(al[mt], sAl + aaddr);
            }
#pragma unroll
            for (int p = 0; p < 4; p++) {
                uint32_t bh[4], bl[4];
                const uint32_t baddr = (uint32_t)(((brow + p * 16) * SST) + kb + bcol_off) * 2;
                ldmx4(bh, sBh + baddr);
                ldmx4(bl, sBl + baddr);
#pragma unroll
                for (int sub = 0; sub < 2; sub++) {
                    const int nt = p * 2 + sub;
                    const uint32_t bh0 = bh[sub * 2], bh1 = bh[sub * 2 + 1];
                    const uint32_t bl0 = bl[sub * 2], bl1 = bl[sub * 2 + 1];
#pragma unroll
                    for (int mt = 0; mt < 2; mt++) {
                        mma16816(acc[mt][nt], ah[mt], bh0, bh1);
                        mma16816(acc[mt][nt], ah[mt], bl0, bl1);
                        mma16816(acc[mt][nt], al[mt], bh0, bh1);
                    }
                }
            }
        }
        __syncthreads();
        if (has) stsA(buf ^ 1);
        buf ^= 1;
    }

    // ---------------- epilogue ----------------
#pragma unroll
    for (int mt = 0; mt < 2; mt++) {
        const int r0 = bm + wm + mt * 16 + lr;
        const bool ok0 = r0 < M, ok1 = (r0 + 8) < M;
#pragma unroll
        for (int nt = 0; nt < 8; nt++) {
            const int col = bn + wn + nt * 8 + lc;
            float2 v0 = make_float2(acc[mt][nt][0], acc[mt][nt][1]);
            float2 v1 = make_float2(acc[mt][nt][2], acc[mt][nt][3]);
            if (flags & 1) {
                float2 bb = *(const float2*)(bias + col);
                v0.x += bb.x; v0.y += bb.y; v1.x += bb.x; v1.y += bb.y;
            }
            if (flags & 2) {
                v0.x = fmaxf(v0.x, 0.f); v0.y = fmaxf(v0.y, 0.f);
                v1.x = fmaxf(v1.x, 0.f); v1.y = fmaxf(v1.y, 0.f);
            }
            if (ok0) *(float2*)(C + (size_t)r0 * N + col) = v0;
            if (ok1) *(float2*)(C + (size_t)(r0 + 8) * N + col) = v1;
            if (flags & 8) {
                float s0 = (ok0 ? v0.x : 0.f) + (ok1 ? v1.x : 0.f);
                float s1 = (ok0 ? v0.y : 0.f) + (ok1 ? v1.y : 0.f);
                float q0 = (ok0 ? v0.x * v0.x : 0.f) + (ok1 ? v1.x * v1.x : 0.f);
                float q1 = (ok0 ? v0.y * v0.y : 0.f) + (ok1 ? v1.y * v1.y : 0.f);
                const int cc = wn + nt * 8 + lc;
                atomicAdd(&cs[cc], s0); atomicAdd(&cs[cc + 1], s1);
                atomicAdd(&cq[cc], q0); atomicAdd(&cq[cc + 1], q1);
            }
            acc[mt][nt][0] = v0.x; acc[mt][nt][1] = v0.y;
            acc[mt][nt][2] = v1.x; acc[mt][nt][3] = v1.y;
        }
    }
    if (flags & 4) {
        // fused ls: CTA's 128 cols = one head (N=512); per-row smem reduce, exclusive store
        const int head = bn >> 7;
#pragma unroll
        for (int mt = 0; mt < 2; mt++) {
            const int rl = wm + mt * 16 + lr;
            float p0 = 0.f, p8 = 0.f;
#pragma unroll
            for (int nt = 0; nt < 8; nt++) {
                const int c = wn + nt * 8 + lc;
                const float a0 = a_s[head * 128 + c], a1 = a_s[head * 128 + c + 1];
                p0 += acc[mt][nt][0] * a0 + acc[mt][nt][1] * a1;
                p8 += acc[mt][nt][2] * a0 + acc[mt][nt][3] * a1;
            }
            atomicAdd(&sls[rl], p0);
            atomicAdd(&sls[rl + 8], p8);
        }
        __syncthreads();
        if (tid < 128 && bm + tid < M)
            ls_out[(bm + tid) * 4 + head] = sls[tid];
    }
    if (flags & 8) {
        __syncthreads();
        if (tid < 128) {
            ps[blockIdx.y * 128 + tid] = cs[tid];
            pq[blockIdx.y * 128 + tid] = cq[tid];
        }
    }
}

// ---------------- BatchNorm ----------------
__global__ void bn_params_kernel(const float* __restrict__ gamma,
                                 const float* __restrict__ beta,
                                 const float* __restrict__ ps,
                                 const float* __restrict__ pq,
                                 int nb, int M,
                                 float* __restrict__ scale, float* __restrict__ shift) {
    __shared__ double ss[4][128], sq[4][128];
    int c = threadIdx.x & 127, part = threadIdx.x >> 7;
    double s = 0.0, q = 0.0;
    for (int b = part; b < nb; b += 4) { s += ps[b * 128 + c]; q += pq[b * 128 + c]; }
    ss[part][c] = s; sq[part][c] = q;
    __syncthreads();
    if (threadIdx.x < 128) {
        double S = ss[0][c] + ss[1][c] + ss[2][c] + ss[3][c];
        double Q = sq[0][c] + sq[1][c] + sq[2][c] + sq[3][c];
        double mu = S / M;
        double var = Q / M - mu * mu;
        float sc = gamma[c] * rsqrtf((float)var + 1e-5f);
        scale[c] = sc;
        shift[c] = beta[c] - (float)mu * sc;
    }
}

// BN apply; wld!=null: also compute ld_out (warp-per-row reduce)
__global__ void bn_apply_kernel(float* __restrict__ h, int M,
                                const float* __restrict__ scale,
                                const float* __restrict__ shift,
                                const float* __restrict__ wld,
                                float* __restrict__ ld_out) {
    int i = blockIdx.x * blockDim.x + threadIdx.x;
    if (i >= M * (CH / 4)) return;
    int c = (i & 31) * 4;
    float4 v = ((float4*)h)[i];
    v.x = v.x * scale[c + 0] + shift[c + 0];
    v.y = v.y * scale[c + 1] + shift[c + 1];
    v.z = v.z * scale[c + 2] + shift[c + 2];
    v.w = v.w * scale[c + 3] + shift[c + 3];
    ((float4*)h)[i] = v;
    if (wld) {
        float4 w0 = ((const float4*)wld)[c + 0];
        float4 w1 = ((const float4*)wld)[c + 1];
        float4 w2 = ((const float4*)wld)[c + 2];
        float4 w3 = ((const float4*)wld)[c + 3];
        float p0 = v.x * w0.x + v.y * w1.x + v.z * w2.x + v.w * w3.x;
        float p1 = v.x * w0.y + v.y * w1.y + v.z * w2.y + v.w * w3.y;
        float p2 = v.x * w0.z + v.y * w1.z + v.z * w2.z + v.w * w3.z;
        float p3 = v.x * w0.w + v.y * w1.w + v.z * w2.w + v.w * w3.w;
#pragma unroll
        for (int off = 16; off > 0; off >>= 1) {
            p0 += __shfl_xor_sync(0xffffffffu, p0, off);
            p1 += __shfl_xor_sync(0xffffffffu, p1, off);
            p2 += __shfl_xor_sync(0xffffffffu, p2, off);
            p3 += __shfl_xor_sync(0xffffffffu, p3, off);
        }
        if ((i & 31) == 0) ((float4*)ld_out)[i >> 5] = make_float4(p0, p1, p2, p3);
    }
}

// ---------------- GAT pieces ----------------
// one warp per (k, h) output: out[k*4+h] = <Wd[k, h*128 : h*128+128], ad[h]>
__global__ void wld_kernel(const float* __restrict__ Wd, const float* __restrict__ ad,
                           float* __restrict__ out) {
    int w = (blockIdx.x * blockDim.x + threadIdx.x) >> 5;
    int lane = threadIdx.x & 31;
    if (w >= 512) return;
    int k = w >> 2, h = w & 3;
    float4 a = ((const float4*)(Wd + (size_t)k * 512 + h * 128))[lane];
    float4 b = ((const float4*)(ad + h * 128))[lane];
    float s = a.x * b.x + a.y * b.y + a.z * b.z + a.w * b.w;
#pragma unroll
    for (int off = 16; off > 0; off >>= 1)
        s += __shfl_xor_sync(0xffffffffu, s, off);
    if (lane == 0) out[k * 4 + h] = s;
}

// merged softmax-numerator + denom pass
__global__ void gat_edge_kernel(const int* __restrict__ src, const int* __restrict__ dst,
                                const float* __restrict__ ls, const float* __restrict__ ld,
                                float* __restrict__ denom, float* __restrict__ logits,
                                int E, int n_loop) {
    int e = blockIdx.x * blockDim.x + threadIdx.x;
    if (e >= E + n_loop) return;
    int s, d; bool mask;
    if (e < E) { s = src[e]; d = dst[e]; mask = (s != d); }
    else       { s = d = e - E; mask = true; }
    float4 a = ((const float4*)ls)[s];
    float4 b = ((const float4*)ld)[d];
    float p0 = mask ? expf(leaky(a.x + b.x)) : 0.f;
    float p1 = mask ? expf(leaky(a.y + b.y)) : 0.f;
    float p2 = mask ? expf(leaky(a.z + b.z)) : 0.f;
    float p3 = mask ? expf(leaky(a.w + b.w)) : 0.f;
    ((float4*)logits)[e] = make_float4(p0, p1, p2, p3);
    atomicAdd(&denom[d * 4 + 0], p0);
    atomicAdd(&denom[d * 4 + 1], p1);
    atomicAdd(&denom[d * 4 + 2], p2);
    atomicAdd(&denom[d * 4 + 3], p3);
}

__global__ void gat_pass3_kernel(const int* __restrict__ src, const int* __restrict__ dst,
                                 const float* __restrict__ logits,
                                 const float* __restrict__ denom,
                                 float* __restrict__ agg, int E, int n_loop) {
    int w = (blockIdx.x * blockDim.x + threadIdx.x) >> 5;
    int lane = threadIdx.x & 31;
    if (w >= E + n_loop) return;
    int s, d;
    if (w < E) { s = src[w]; d = dst[w]; }
    else       { s = d = w - E; }
    float4 P = ((const float4*)logits)[w];
    float4 D = ((const float4*)denom)[d];
    float a0 = 0.25f * P.x / (D.x > 0.f ? D.x : 1.f);
    float a1 = 0.25f * P.y / (D.y > 0.f ? D.y : 1.f);
    float a2 = 0.25f * P.z / (D.z > 0.f ? D.z : 1.f);
    float a3 = 0.25f * P.w / (D.w > 0.f ? D.w : 1.f);
    const float4* xr = (const float4*)g_xs + (size_t)s * 128;
    float4 x0 = xr[lane], x1 = xr[32 + lane], x2 = xr[64 + lane], x3 = xr[96 + lane];
    float r0 = a0 * x0.x + a1 * x1.x + a2 * x2.x + a3 * x3.x;
    float r1 = a0 * x0.y + a1 * x1.y + a2 * x2.y + a3 * x3.y;
    float r2 = a0 * x0.z + a1 * x1.z + a2 * x2.z + a3 * x3.z;
    float r3 = a0 * x0.w + a1 * x1.w + a2 * x2.w + a3 * x3.w;
    float* out = agg + (size_t)d * CH + lane * 4;
    asm volatile("red.global.add.v4.f32 [%0], {%1, %2, %3, %4};"
                 :: "l"(out), "f"(r0), "f"(r1), "f"(r2), "f"(r3) : "memory");
}

// combine; wld!=null: also compute ld_out for next relation
__global__ void combine_kernel(float* __restrict__ gene, const float* __restrict__ bias,
                               const float* __restrict__ agg,
                               const float* __restrict__ wld, float* __restrict__ ld_out) {
    int i = blockIdx.x * blockDim.x + threadIdx.x;
    if (i >= NGENE * 32) return;
    int c = (i & 31) * 4;
    float4 v = ((float4*)gene)[i];
    float4 ag = ((const float4*)agg)[i];
    v.x += ag.x + bias[c + 0];
    v.y += ag.y + bias[c + 1];
    v.z += ag.z + bias[c + 2];
    v.w += ag.w + bias[c + 3];
    ((float4*)gene)[i] = v;
    if (wld) {
        float4 w0 = ((const float4*)wld)[c + 0];
        float4 w1 = ((const float4*)wld)[c + 1];
        float4 w2 = ((const float4*)wld)[c + 2];
        float4 w3 = ((const float4*)wld)[c + 3];
        float p0 = v.x * w0.x + v.y * w1.x + v.z * w2.x + v.w * w3.x;
        float p1 = v.x * w0.y + v.y * w1.y + v.z * w2.y + v.w * w3.y;
        float p2 = v.x * w0.z + v.y * w1.z + v.z * w2.z + v.w * w3.z;
        float p3 = v.x * w0.w + v.y * w1.w + v.z * w2.w + v.w * w3.w;
#pragma unroll
        for (int off = 16; off > 0; off >>= 1) {
            p0 += __shfl_xor_sync(0xffffffffu, p0, off);
            p1 += __shfl_xor_sync(0xffffffffu, p1, off);
            p2 += __shfl_xor_sync(0xffffffffu, p2, off);
            p3 += __shfl_xor_sync(0xffffffffu, p3, off);
        }
        if ((i & 31) == 0) ((float4*)ld_out)[i >> 5] = make_float4(p0, p1, p2, p3);
    }
}

// ---------------- launch ----------------
#define SYM(p, s) cudaGetSymbolAddress((void**)&p, s)

extern "C" void kernel_launch(void* const* d_in, const int* in_sizes, int n_in,
                              void* d_out, int out_size) {
    const float* x_gene = (const float*)d_in[0];
    const float* x_dis  = (const float*)d_in[1];
    const int* e1_src = (const int*)d_in[2];
    const int* e1_dst = (const int*)d_in[3];
    const int* e2_src = (const int*)d_in[4];
    const int* e2_dst = (const int*)d_in[5];
    const float* Wg = (const float*)d_in[6];
    const float* bg = (const float*)d_in[7];
    const float* gg = (const float*)d_in[8];
    const float* betag = (const float*)d_in[9];
    const float* Wd = (const float*)d_in[10];
    const float* bd = (const float*)d_in[11];
    const float* gd = (const float*)d_in[12];
    const float* betad = (const float*)d_in[13];
    const float* W1s = (const float*)d_in[14];
    const float* W1d = (const float*)d_in[15];
    const float* a1s = (const float*)d_in[16];
    const float* a1d = (const float*)d_in[17];
    const float* b1  = (const float*)d_in[18];
    const float* W2s = (const float*)d_in[19];
    const float* W2d = (const float*)d_in[20];
    const float* a2s = (const float*)d_in[21];
    const float* a2d = (const float*)d_in[22];
    const float* b2  = (const float*)d_in[23];

    float* out_gene = (float*)d_out;
    float* out_dis  = (float*)d_out + (size_t)NGENE * CH;

    float *xs, *agg1, *agg2, *ls1, *ls2, *ld1, *ld2, *lg1, *lg2, *dn1, *dn2;
    float *wld1, *wld2, *psG, *pqG, *psD, *pqD, *scG, *shG, *scD, *shD;
    __nv_bfloat16 *btg_h, *btg_l, *btd_h, *btd_l, *bt1_h, *bt1_l, *bt2_h, *bt2_l;
    SYM(xs, g_xs); SYM(agg1, g_agg1); SYM(agg2, g_agg2);
    SYM(ls1, g_ls1); SYM(ls2, g_ls2); SYM(ld1, g_ld1); SYM(ld2, g_ld2);
    SYM(lg1, g_logits1); SYM(lg2, g_logits2); SYM(dn1, g_denom1); SYM(dn2, g_denom2);
    SYM(wld1, g_wld1); SYM(wld2, g_wld2);
    SYM(psG, g_psG); SYM(pqG, g_pqG); SYM(psD, g_psD); SYM(pqD, g_pqD);
    SYM(scG, g_scaleG); SYM(shG, g_shiftG); SYM(scD, g_scaleD); SYM(shD, g_shiftD);
    SYM(btg_h, g_btg_hi); SYM(btg_l, g_btg_lo); SYM(btd_h, g_btd_hi); SYM(btd_l, g_btd_lo);
    SYM(bt1_h, g_bt1_hi); SYM(bt1_l, g_bt1_lo); SYM(bt2_h, g_bt2_hi); SYM(bt2_l, g_bt2_lo);

    cudaStream_t s1, s2;
    cudaStreamCreateWithFlags(&s1, cudaStreamNonBlocking);
    cudaStreamCreateWithFlags(&s2, cudaStreamNonBlocking);
    cudaEvent_t e0, e_wld1, e_xs1, e_misc2, e_z1, e_z2;
    cudaEventCreateWithFlags(&e0, cudaEventDisableTiming);
    cudaEventCreateWithFlags(&e_wld1, cudaEventDisableTiming);
    cudaEventCreateWithFlags(&e_xs1, cudaEventDisableTiming);
    cudaEventCreateWithFlags(&e_misc2, cudaEventDisableTiming);
    cudaEventCreateWithFlags(&e_z1, cudaEventDisableTiming);
    cudaEventCreateWithFlags(&e_z2, cudaEventDisableTiming);

    cudaEventRecord(e0, 0);
    cudaStreamWaitEvent(s1, e0, 0);
    cudaStreamWaitEvent(s2, e0, 0);

    const int GY_G = (NGENE + 127) / 128;   // 391
    const int GY_D = (NDIS + 127) / 128;    // 196

    // ---- s2: misc small kernels + zeroing ----
    wld_kernel<<<64, 256, 0, s2>>>(W1d, a1d, wld1);
    cudaEventRecord(e_wld1, s2);
    wld_kernel<<<64, 256, 0, s2>>>(W2d, a2d, wld2);
    split_bt_kernel<<<(CH * 512 + 255) / 256, 256, 0, s2>>>(W2s, bt2_h, bt2_l, CH, 512);
    cudaEventRecord(e_misc2, s2);
    cudaMemsetAsync(dn1, 0, NGENE * 4 * sizeof(float), s2);
    cudaMemsetAsync(agg1, 0, (size_t)NGENE * CH * sizeof(float), s2);
    cudaEventRecord(e_z1, s2);
    cudaMemsetAsync(dn2, 0, NGENE * 4 * sizeof(float), s2);
    cudaMemsetAsync(agg2, 0, (size_t)NGENE * CH * sizeof(float), s2);
    cudaEventRecord(e_z2, s2);

    // ---- s1: dis encode + xs1 GEMM (no init dependency) ----
    split_bt_kernel<<<(FDIS * CH + 255) / 256, 256, 0, s1>>>(Wd, btd_h, btd_l, FDIS, CH);
    gemm_mma_kernel<<<dim3(1, GY_D), 256, 0, s1>>>(
        x_dis, btd_h, btd_l, bd, nullptr, nullptr, psD, pqD, out_dis, NDIS, CH, FDIS, 1 | 2 | 8);
    bn_params_kernel<<<1, 512, 0, s1>>>(gd, betad, psD, pqD, GY_D, NDIS, scD, shD);
    bn_apply_kernel<<<(NDIS * 32 + 255) / 256, 256, 0, s1>>>(out_dis, NDIS, scD, shD,
                                                             nullptr, nullptr);
    split_bt_kernel<<<(CH * 512 + 255) / 256, 256, 0, s1>>>(W1s, bt1_h, bt1_l, CH, 512);
    gemm_mma_kernel<<<dim3(4, GY_D), 256, 0, s1>>>(
        out_dis, bt1_h, bt1_l, nullptr, a1s, ls1, nullptr, nullptr, xs, NDIS, 512, CH, 4);
    cudaEventRecord(e_xs1, s1);

    // ---- s0: gene encode ----
    split_bt_kernel<<<(FGENE * CH + 255) / 256, 256>>>(Wg, btg_h, btg_l, FGENE, CH);
    gemm_mma_kernel<<<dim3(1, GY_G), 256>>>(
        x_gene, btg_h, btg_l, bg, nullptr, nullptr, psG, pqG, out_gene, NGENE, CH, FGENE, 1 | 2 | 8);
    bn_params_kernel<<<1, 512>>>(gg, betag, psG, pqG, GY_G, NGENE, scG, shG);
    cudaStreamWaitEvent(0, e_wld1, 0);
    bn_apply_kernel<<<(NGENE * 32 + 255) / 256, 256>>>(out_gene, NGENE, scG, shG, wld1, ld1);

    // ---- relation 1 on s0 ----
    cudaStreamWaitEvent(0, e_xs1, 0);
    cudaStreamWaitEvent(0, e_z1, 0);
    {
        const int E = NE, n_loop = NDIS, ET = E + n_loop;
        gat_edge_kernel<<<(ET + 255) / 256, 256>>>(e1_src, e1_dst, ls1, ld1, dn1, lg1, E, n_loop);
        gat_pass3_kernel<<<(ET + 7) / 8, 256>>>(e1_src, e1_dst, lg1, dn1, agg1, E, n_loop);
    }
    cudaStreamWaitEvent(0, e_misc2, 0);
    combine_kernel<<<(NGENE * 32 + 255) / 256, 256>>>(out_gene, b1, agg1, wld2, ld2);

    // ---- relation 2 on s0 ----
    gemm_mma_kernel<<<dim3(4, GY_G), 256>>>(
        out_gene, bt2_h, bt2_l, nullptr, a2s, ls2, nullptr, nullptr, xs, NGENE, 512, CH, 4);
    cudaStreamWaitEvent(0, e_z2, 0);
    {
        const int E = NE, n_loop = NGENE, ET = E + n_loop;
        gat_edge_kernel<<<(ET + 255) / 256, 256>>>(e2_src, e2_dst, ls2, ld2, dn2, lg2, E, n_loop);
        gat_pass3_kernel<<<(ET + 7) / 8, 256>>>(e2_src, e2_dst, lg2, dn2, agg2, E, n_loop);
    }
    combine_kernel<<<(NGENE * 32 + 255) / 256, 256>>>(out_gene, b2, agg2, nullptr, nullptr);

    cudaEventDestroy(e0);
    cudaEventDestroy(e_wld1);
    cudaEventDestroy(e_xs1);
    cudaEventDestroy(e_misc2);
    cudaEventDestroy(e_z1);
    cudaEventDestroy(e_z2);
    cudaStreamDestroy(s1);
    cudaStreamDestroy(s2);
}